// round 10
// baseline (speedup 1.0000x reference)
#include <cuda_runtime.h>
#include <cstdint>
#include <math.h>

#define N_NODES 100000
#define N_EDGES 1280000
#define DIM 64

// Scratch (allocation-free rule). Zero-initialized at load; gemm resets both
// arrays every call (sole-reader zero-after-read), so no zero kernel ever.
__device__ float g_agg[(size_t)N_NODES * DIM];   // 25.6 MB
__device__ float g_deg[N_NODES];

// ---------------------------------------------------------------------------
// Kernel 1: edge scatter (measured-best form, ~70.6us).  16 threads/edge, one
// float4 gather + one vector RED each; warp covers 2 edges fully coalesced.
// ---------------------------------------------------------------------------
__global__ __launch_bounds__(256) void edge_kernel(
    const float* __restrict__ feat,
    const float* __restrict__ w,
    const int*   __restrict__ src,
    const int*   __restrict__ dst)
{
    unsigned t    = blockIdx.x * blockDim.x + threadIdx.x;
    unsigned e    = t >> 4;
    unsigned lane = t & 15;
    if (e >= N_EDGES) return;

    int   s  = __ldg(src + e);
    int   d  = __ldg(dst + e);
    float we = __ldg(w + e);

    float4 f = __ldg((const float4*)(feat + (size_t)s * DIM) + lane);
    f.x *= we; f.y *= we; f.z *= we; f.w *= we;

    float* p = g_agg + (size_t)d * DIM + lane * 4;
    asm volatile("red.global.add.v4.f32 [%0], {%1,%2,%3,%4};"
                 :: "l"(p), "f"(f.x), "f"(f.y), "f"(f.z), "f"(f.w)
                 : "memory");

    if (lane == 0) atomicAdd(g_deg + d, 1.0f);
}

// ---------------------------------------------------------------------------
// Kernel 2: tensor-core GEMM via mma.sync.m16n8k8 tf32 (baseline PTX, sm_80+).
// 3-pass hi/lo split (hi*hi + hi*lo + lo*hi) => fp32-class accuracy (~1e-7).
//   out[r] = dinv[r] * (g_agg[r] @ W)
// Tile 128 rows x 64 cols, 256 threads = 8 warps, warp = 32x32 subtile.
// Smem stride 68 floats -> conflict-free A-frag and B-frag reads.
// Loader zeroes g_agg after reading; g_deg reset after epilogue sync.
// ---------------------------------------------------------------------------
#define TROWS 128
#define ASTR 68          // A smem row stride (floats)
#define BSTR 68          // B smem row stride (floats)
#define SM_AH 0
#define SM_AL (SM_AH + 128 * ASTR)
#define SM_BH (SM_AL + 128 * ASTR)
#define SM_BL (SM_BH + DIM * BSTR)
#define SM_FLOATS (SM_BL + DIM * BSTR)
#define SM_BYTES (SM_FLOATS * 4)

__device__ __forceinline__ float tf32_rna(float x) {
    float r;
    asm("cvt.rna.tf32.f32 %0, %1;" : "=f"(r) : "f"(x));
    return r;
}

__device__ __forceinline__ void mma_tf32(float c[4],
                                         uint32_t a0, uint32_t a1, uint32_t a2, uint32_t a3,
                                         uint32_t b0, uint32_t b1) {
    asm volatile(
        "mma.sync.aligned.m16n8k8.row.col.f32.tf32.tf32.f32 "
        "{%0,%1,%2,%3}, {%4,%5,%6,%7}, {%8,%9}, {%0,%1,%2,%3};"
        : "+f"(c[0]), "+f"(c[1]), "+f"(c[2]), "+f"(c[3])
        : "r"(a0), "r"(a1), "r"(a2), "r"(a3), "r"(b0), "r"(b1));
}

__global__ __launch_bounds__(256) void gemm_mma_kernel(
    const float* __restrict__ Wm,      // [64,64] row-major (k, c)
    float*       __restrict__ out)     // [N, 64]
{
    extern __shared__ float sm[];
    float* AH = sm + SM_AH;            // [128][ASTR]  A hi
    float* AL = sm + SM_AL;            // [128][ASTR]  A lo
    float* BH = sm + SM_BH;            // [64][BSTR]   B hi (as W[k][n])
    float* BL = sm + SM_BL;            // [64][BSTR]   B lo

    const int tid   = threadIdx.x;
    const int rbase = blockIdx.x * TROWS;

    // ---- Load A rows, split hi/lo, reset g_agg (sole reader per float4) ----
    {
        const int row  = tid >> 1;                 // 0..127
        const int half = tid & 1;                  // 8 float4 per half-row
        const int gr   = rbase + row;
        const bool valid = (gr < N_NODES);
        float4* ap = (float4*)(g_agg + (size_t)gr * DIM) + half * 8;
        const float4 z4 = make_float4(0.f, 0.f, 0.f, 0.f);
        float* ahr = AH + row * ASTR + half * 32;
        float* alr = AL + row * ASTR + half * 32;
        #pragma unroll
        for (int q = 0; q < 8; q++) {
            float4 v = valid ? __ldg(ap + q) : z4;
            float4 h = make_float4(tf32_rna(v.x), tf32_rna(v.y),
                                   tf32_rna(v.z), tf32_rna(v.w));
            float4 l = make_float4(tf32_rna(v.x - h.x), tf32_rna(v.y - h.y),
                                   tf32_rna(v.z - h.z), tf32_rna(v.w - h.w));
            *(float4*)(ahr + q * 4) = h;
            *(float4*)(alr + q * 4) = l;
            if (valid) ap[q] = z4;                 // reset for next call
        }
    }

    // ---- Load B = W (k-major [k][n]), split hi/lo ----
    {
        #pragma unroll
        for (int i = tid; i < DIM * DIM; i += 256) {
            const int k = i >> 6, n = i & 63;
            float v = __ldg(Wm + i);
            float h = tf32_rna(v);
            BH[k * BSTR + n] = h;
            BL[k * BSTR + n] = tf32_rna(v - h);
        }
    }
    __syncthreads();

    // ---- Compute: warp w covers rows 32*(w>>1)..+31, cols 32*(w&1)..+31 ----
    const int wid = tid >> 5;
    const int lane = tid & 31;
    const int g   = lane >> 2;         // group id (row within frag)
    const int tig = lane & 3;          // thread-in-group (k / col pair)
    const int wr  = 32 * (wid >> 1);
    const int wn  = 32 * (wid & 1);

    float acc[2][4][4];
    #pragma unroll
    for (int m = 0; m < 2; m++)
        #pragma unroll
        for (int j = 0; j < 4; j++)
            #pragma unroll
            for (int q = 0; q < 4; q++) acc[m][j][q] = 0.f;

    const float* Abuf[3] = {AH, AH, AL};
    const float* Bbuf[3] = {BH, BL, BH};

    #pragma unroll
    for (int p = 0; p < 3; p++) {
        const float* A = Abuf[p];
        const float* B = Bbuf[p];
        #pragma unroll
        for (int kc = 0; kc < 8; kc++) {
            const int kk = kc * 8;
            // B frags for 4 n-tiles
            uint32_t b0[4], b1[4];
            #pragma unroll
            for (int j = 0; j < 4; j++) {
                const int n = wn + j * 8 + g;
                b0[j] = __float_as_uint(B[(kk + tig)     * BSTR + n]);
                b1[j] = __float_as_uint(B[(kk + tig + 4) * BSTR + n]);
            }
            // A frags + mma for 2 m-tiles
            #pragma unroll
            for (int m = 0; m < 2; m++) {
                const int r0 = wr + m * 16 + g;
                uint32_t a0 = __float_as_uint(A[(r0)     * ASTR + kk + tig]);
                uint32_t a1 = __float_as_uint(A[(r0 + 8) * ASTR + kk + tig]);
                uint32_t a2 = __float_as_uint(A[(r0)     * ASTR + kk + tig + 4]);
                uint32_t a3 = __float_as_uint(A[(r0 + 8) * ASTR + kk + tig + 4]);
                #pragma unroll
                for (int j = 0; j < 4; j++)
                    mma_tf32(acc[m][j], a0, a1, a2, a3, b0[j], b1[j]);
            }
        }
    }

    // ---- Epilogue: scale by dinv, store; then reset g_deg ----
    #pragma unroll
    for (int m = 0; m < 2; m++) {
        const int r0 = rbase + wr + m * 16 + g;
        const int r1 = r0 + 8;
        float dinv0 = 0.f, dinv1 = 0.f;
        if (r0 < N_NODES) dinv0 = 1.0f / fmaxf(g_deg[r0], 1.0f);
        if (r1 < N_NODES) dinv1 = 1.0f / fmaxf(g_deg[r1], 1.0f);
        #pragma unroll
        for (int j = 0; j < 4; j++) {
            const int col = wn + j * 8 + tig * 2;
            if (r0 < N_NODES)
                *(float2*)(out + (size_t)r0 * DIM + col) =
                    make_float2(acc[m][j][0] * dinv0, acc[m][j][1] * dinv0);
            if (r1 < N_NODES)
                *(float2*)(out + (size_t)r1 * DIM + col) =
                    make_float2(acc[m][j][2] * dinv1, acc[m][j][3] * dinv1);
        }
    }

    __syncthreads();
    {
        const int gr = rbase + tid;
        if (tid < TROWS && gr < N_NODES) g_deg[gr] = 0.f;   // reset for next call
    }
}

// ---------------------------------------------------------------------------
// kernel_launch: edge scatter -> tensor-core gemm (+normalize +scratch reset).
// Inputs (metadata order): features, w, W, src, dst.  Output: float [N, 64].
// ---------------------------------------------------------------------------
extern "C" void kernel_launch(void* const* d_in, const int* in_sizes, int n_in,
                              void* d_out, int out_size)
{
    const float* feat = (const float*)d_in[0];
    const float* w    = (const float*)d_in[1];
    const float* Wm   = (const float*)d_in[2];
    const int*   src  = (const int*)d_in[3];
    const int*   dst  = (const int*)d_in[4];
    float*       out  = (float*)d_out;

    static bool attr_done = false;
    if (!attr_done) {
        cudaFuncSetAttribute(gemm_mma_kernel,
                             cudaFuncAttributeMaxDynamicSharedMemorySize, SM_BYTES);
        attr_done = true;
    }

    {
        long long threads = (long long)N_EDGES * 16;
        int grid = (int)((threads + 255) / 256);
        edge_kernel<<<grid, 256>>>(feat, w, src, dst);
    }
    {
        int grid = (N_NODES + TROWS - 1) / TROWS;
        gemm_mma_kernel<<<grid, 256, SM_BYTES>>>(Wm, out);
    }
}

// round 12
// speedup vs baseline: 1.0180x; 1.0180x over previous
#include <cuda_runtime.h>
#include <cstdint>
#include <math.h>

#define N_NODES 100000
#define N_EDGES 1280000
#define DIM 64

// Scratch (allocation-free rule). Zero-initialized at load; gemm resets both
// arrays every call (sole-reader zero-after-read), so no zero kernel ever.
__device__ float g_agg[(size_t)N_NODES * DIM];   // 25.6 MB
__device__ float g_deg[N_NODES];

// ---------------------------------------------------------------------------
// Kernel 1: edge scatter (measured-best form, ~72us).  16 threads/edge, one
// float4 gather + one vector RED each; warp covers 2 edges fully coalesced.
// ---------------------------------------------------------------------------
__global__ __launch_bounds__(256) void edge_kernel(
    const float* __restrict__ feat,
    const float* __restrict__ w,
    const int*   __restrict__ src,
    const int*   __restrict__ dst)
{
    unsigned t    = blockIdx.x * blockDim.x + threadIdx.x;
    unsigned e    = t >> 4;
    unsigned lane = t & 15;
    if (e >= N_EDGES) return;

    int   s  = __ldg(src + e);
    int   d  = __ldg(dst + e);
    float we = __ldg(w + e);

    float4 f = __ldg((const float4*)(feat + (size_t)s * DIM) + lane);
    f.x *= we; f.y *= we; f.z *= we; f.w *= we;

    float* p = g_agg + (size_t)d * DIM + lane * 4;
    asm volatile("red.global.add.v4.f32 [%0], {%1,%2,%3,%4};"
                 :: "l"(p), "f"(f.x), "f"(f.y), "f"(f.z), "f"(f.w)
                 : "memory");

    if (lane == 0) atomicAdd(g_deg + d, 1.0f);
}

// ---------------------------------------------------------------------------
// Kernel 2: tensor-core GEMM, mma.sync.m16n8k8 tf32, 3-pass hi/lo split.
// hi/lo INTERLEAVED in smem: [row][2k]=hi, [row][2k+1]=lo.  One LDS.64 per
// fragment element feeds all 3 passes -> 128 LDS/warp/k-sweep (was 384).
// Stride 136 floats: within each 16-lane phase, A (8g+2tig) and B (8tig+2g)
// hit distinct bank-pairs -> conflict-free 64-bit LDS.
//   out[r] = dinv[r] * (g_agg[r] @ W)
// Tile 128x64, 256 thr = 8 warps (warp = 32x32 subtile).
// ---------------------------------------------------------------------------
#define TROWS 128
#define STR 136                         // floats; 136 % 32 == 8, %4 == 0
#define SM_A2 0
#define SM_B2 (SM_A2 + 128 * STR)
#define SM_FLOATS (SM_B2 + DIM * STR)
#define SM_BYTES (SM_FLOATS * 4)        // 104448 B -> 2 CTA/SM

__device__ __forceinline__ float tf32_rna(float x) {
    float r;
    asm("cvt.rna.tf32.f32 %0, %1;" : "=f"(r) : "f"(x));
    return r;
}

__device__ __forceinline__ void mma_tf32(float c[4],
                                         uint32_t a0, uint32_t a1, uint32_t a2, uint32_t a3,
                                         uint32_t b0, uint32_t b1) {
    asm volatile(
        "mma.sync.aligned.m16n8k8.row.col.f32.tf32.tf32.f32 "
        "{%0,%1,%2,%3}, {%4,%5,%6,%7}, {%8,%9}, {%0,%1,%2,%3};"
        : "+f"(c[0]), "+f"(c[1]), "+f"(c[2]), "+f"(c[3])
        : "r"(a0), "r"(a1), "r"(a2), "r"(a3), "r"(b0), "r"(b1));
}

__global__ __launch_bounds__(256, 2) void gemm_mma_kernel(
    const float* __restrict__ Wm,      // [64,64] row-major (k, c)
    float*       __restrict__ out)     // [N, 64]
{
    extern __shared__ float sm[];
    float* A2 = sm + SM_A2;            // [128][STR] pairs (hi,lo) along 2k
    float* B2 = sm + SM_B2;            // [64][STR]  pairs (hi,lo) along 2n

    const int tid   = threadIdx.x;
    const int rbase = blockIdx.x * TROWS;

    // ---- Load A rows, split hi/lo interleaved, reset g_agg ----
    {
        const int row  = tid >> 1;                 // 0..127
        const int half = tid & 1;                  // k-half: 8 float4 each
        const int gr   = rbase + row;
        const bool valid = (gr < N_NODES);
        float4* ap = (float4*)(g_agg + (size_t)gr * DIM) + half * 8;
        const float4 z4 = make_float4(0.f, 0.f, 0.f, 0.f);
        float* arow = A2 + row * STR + half * 64;  // 2k offset
        #pragma unroll
        for (int q = 0; q < 8; q++) {
            float4 v = valid ? __ldg(ap + q) : z4;
            float hx = tf32_rna(v.x), hy = tf32_rna(v.y),
                  hz = tf32_rna(v.z), hw = tf32_rna(v.w);
            *(float4*)(arow + q * 8)     = make_float4(hx, tf32_rna(v.x - hx),
                                                       hy, tf32_rna(v.y - hy));
            *(float4*)(arow + q * 8 + 4) = make_float4(hz, tf32_rna(v.z - hz),
                                                       hw, tf32_rna(v.w - hw));
            if (valid) ap[q] = z4;                 // sole reader: reset
        }
    }

    // ---- Load B = W (k-major [k][n]), split hi/lo interleaved ----
    {
        #pragma unroll
        for (int i = tid; i < DIM * DIM; i += 256) {
            const int k = i >> 6, n = i & 63;
            float v = __ldg(Wm + i);
            float h = tf32_rna(v);
            *(float2*)(B2 + k * STR + 2 * n) = make_float2(h, tf32_rna(v - h));
        }
    }
    __syncthreads();

    // ---- Compute: warp w covers rows 32*(w>>1)..+31, cols 32*(w&1)..+31 ----
    const int wid  = tid >> 5;
    const int lane = tid & 31;
    const int g    = lane >> 2;        // fragment row group
    const int tig  = lane & 3;         // thread-in-group (k index)
    const int wr   = 32 * (wid >> 1);
    const int wn   = 32 * (wid & 1);

    float acc[2][4][4];
    #pragma unroll
    for (int m = 0; m < 2; m++)
        #pragma unroll
        for (int j = 0; j < 4; j++)
            #pragma unroll
            for (int q = 0; q < 4; q++) acc[m][j][q] = 0.f;

    #pragma unroll 2
    for (int kc = 0; kc < 8; kc++) {
        const int kk = kc * 8;
        // A fragment pairs for 2 m-tiles (each load = (hi,lo))
        float2 a0[2], a1[2], a2[2], a3[2];
        #pragma unroll
        for (int m = 0; m < 2; m++) {
            const int r0 = wr + m * 16 + g;
            a0[m] = *(const float2*)(A2 + (r0)     * STR + 2 * (kk + tig));
            a1[m] = *(const float2*)(A2 + (r0 + 8) * STR + 2 * (kk + tig));
            a2[m] = *(const float2*)(A2 + (r0)     * STR + 2 * (kk + tig + 4));
            a3[m] = *(const float2*)(A2 + (r0 + 8) * STR + 2 * (kk + tig + 4));
        }
        #pragma unroll
        for (int j = 0; j < 4; j++) {
            const int n = wn + j * 8 + g;
            float2 b0 = *(const float2*)(B2 + (kk + tig)     * STR + 2 * n);
            float2 b1 = *(const float2*)(B2 + (kk + tig + 4) * STR + 2 * n);
            #pragma unroll
            for (int m = 0; m < 2; m++) {
                // hi*hi
                mma_tf32(acc[m][j],
                         __float_as_uint(a0[m].x), __float_as_uint(a1[m].x),
                         __float_as_uint(a2[m].x), __float_as_uint(a3[m].x),
                         __float_as_uint(b0.x), __float_as_uint(b1.x));
                // hi*lo
                mma_tf32(acc[m][j],
                         __float_as_uint(a0[m].x), __float_as_uint(a1[m].x),
                         __float_as_uint(a2[m].x), __float_as_uint(a3[m].x),
                         __float_as_uint(b0.y), __float_as_uint(b1.y));
                // lo*hi
                mma_tf32(acc[m][j],
                         __float_as_uint(a0[m].y), __float_as_uint(a1[m].y),
                         __float_as_uint(a2[m].y), __float_as_uint(a3[m].y),
                         __float_as_uint(b0.x), __float_as_uint(b1.x));
            }
        }
    }

    // ---- Epilogue: scale by dinv, store; then reset g_deg ----
    #pragma unroll
    for (int m = 0; m < 2; m++) {
        const int r0 = rbase + wr + m * 16 + g;
        const int r1 = r0 + 8;
        float dinv0 = 0.f, dinv1 = 0.f;
        if (r0 < N_NODES) dinv0 = 1.0f / fmaxf(g_deg[r0], 1.0f);
        if (r1 < N_NODES) dinv1 = 1.0f / fmaxf(g_deg[r1], 1.0f);
        #pragma unroll
        for (int j = 0; j < 4; j++) {
            const int col = wn + j * 8 + tig * 2;
            if (r0 < N_NODES)
                *(float2*)(out + (size_t)r0 * DIM + col) =
                    make_float2(acc[m][j][0] * dinv0, acc[m][j][1] * dinv0);
            if (r1 < N_NODES)
                *(float2*)(out + (size_t)r1 * DIM + col) =
                    make_float2(acc[m][j][2] * dinv1, acc[m][j][3] * dinv1);
        }
    }

    __syncthreads();
    {
        const int gr = rbase + tid;
        if (tid < TROWS && gr < N_NODES) g_deg[gr] = 0.f;   // reset for next call
    }
}

// ---------------------------------------------------------------------------
// kernel_launch: edge scatter -> tensor-core gemm (+normalize +scratch reset).
// Inputs (metadata order): features, w, W, src, dst.  Output: float [N, 64].
// ---------------------------------------------------------------------------
extern "C" void kernel_launch(void* const* d_in, const int* in_sizes, int n_in,
                              void* d_out, int out_size)
{
    const float* feat = (const float*)d_in[0];
    const float* w    = (const float*)d_in[1];
    const float* Wm   = (const float*)d_in[2];
    const int*   src  = (const int*)d_in[3];
    const int*   dst  = (const int*)d_in[4];
    float*       out  = (float*)d_out;

    static bool attr_done = false;
    if (!attr_done) {
        cudaFuncSetAttribute(gemm_mma_kernel,
                             cudaFuncAttributeMaxDynamicSharedMemorySize, SM_BYTES);
        attr_done = true;
    }

    {
        long long threads = (long long)N_EDGES * 16;
        int grid = (int)((threads + 255) / 256);
        edge_kernel<<<grid, 256>>>(feat, w, src, dst);
    }
    {
        int grid = (N_NODES + TROWS - 1) / TROWS;
        gemm_mma_kernel<<<grid, 256, SM_BYTES>>>(Wm, out);
    }
}

// round 13
// speedup vs baseline: 1.1130x; 1.0933x over previous
#include <cuda_runtime.h>
#include <cuda_fp16.h>
#include <cstdint>
#include <math.h>

#define N_NODES 100000
#define N_EDGES 1280000
#define DIM 64

// Scratch (allocation-free rule).  g_Y fully overwritten every call.
// g_deg zero at load; normalize kernel resets it for the next call.
__device__ __half g_Y[(size_t)N_NODES * DIM];    // 12.8 MB  Y = F @ W (fp16)
__device__ float  g_deg[N_NODES];

// ---------------------------------------------------------------------------
// Kernel 0: zero d_out (RED accumulator; harness poisons it each run).
// ---------------------------------------------------------------------------
__global__ __launch_bounds__(256) void zero_out_kernel(float4* __restrict__ out4) {
    int i = blockIdx.x * blockDim.x + threadIdx.x;
    if (i < N_NODES * DIM / 4)
        out4[i] = make_float4(0.f, 0.f, 0.f, 0.f);
}

// ---------------------------------------------------------------------------
// Kernel 1: Y = F @ W  (fp32 compute, fp16 store).  R4's measured-best SIMT
// structure: 128-row tile, 256 thr, 8x4 register tile, transposed Hsh.
// ---------------------------------------------------------------------------
#define TROWS 128
#define HSTRIDE 132

__global__ __launch_bounds__(256) void gemm_fw_kernel(
    const float* __restrict__ feat,    // [N, 64]
    const float* __restrict__ Wm)      // [64, 64] row-major (k, c)
{
    __shared__ float Wsh[DIM][DIM];        // 16 KB
    __shared__ float Hsh[DIM][HSTRIDE];    // F tile transposed [k][row]

    const int tid   = threadIdx.x;
    const int rbase = blockIdx.x * TROWS;

    #pragma unroll
    for (int i = tid * 4; i < DIM * DIM; i += 256 * 4)
        *(float4*)(&Wsh[0][0] + i) = __ldg((const float4*)(Wm + i));

    {
        const int row  = tid & 127;
        const int seg0 = tid >> 7;                  // 0 or 1
        const int gr   = rbase + row;
        const bool valid = (gr < N_NODES);
        const float4* ap = (const float4*)(feat + (size_t)gr * DIM);
        const float4 z4 = make_float4(0.f, 0.f, 0.f, 0.f);
        #pragma unroll
        for (int j = 0; j < 8; j++) {
            const int seg = seg0 + 2 * j;           // 0..15
            float4 v = valid ? __ldg(ap + seg) : z4;
            const int k = seg * 4;
            Hsh[k + 0][row] = v.x;
            Hsh[k + 1][row] = v.y;
            Hsh[k + 2][row] = v.z;
            Hsh[k + 3][row] = v.w;
        }
    }
    __syncthreads();

    const int ty = tid >> 4;       // 0..15 -> rows 8ty..+7
    const int tx = tid & 15;       // 0..15 -> cols 4tx..+3
    float acc[8][4] = {};

    #pragma unroll 4
    for (int k = 0; k < DIM; k++) {
        float4 a0 = *(const float4*)&Hsh[k][8 * ty];
        float4 a1 = *(const float4*)&Hsh[k][8 * ty + 4];
        float4 b  = *(const float4*)&Wsh[k][4 * tx];
        float ar[8] = {a0.x, a0.y, a0.z, a0.w, a1.x, a1.y, a1.z, a1.w};
        #pragma unroll
        for (int i = 0; i < 8; i++) {
            acc[i][0] += ar[i] * b.x;
            acc[i][1] += ar[i] * b.y;
            acc[i][2] += ar[i] * b.z;
            acc[i][3] += ar[i] * b.w;
        }
    }

    #pragma unroll
    for (int i = 0; i < 8; i++) {
        const int r = rbase + 8 * ty + i;
        if (r < N_NODES) {
            __half2 h01 = __floats2half2_rn(acc[i][0], acc[i][1]);
            __half2 h23 = __floats2half2_rn(acc[i][2], acc[i][3]);
            __half2* py = (__half2*)(g_Y + (size_t)r * DIM + 4 * tx);
            py[0] = h01;                     // 8B total, 8B-aligned
            py[1] = h23;
        }
    }
}

// ---------------------------------------------------------------------------
// Kernel 2: edge scatter on fp16 Y.  16 threads/edge: each lane loads 8B of
// Y[src] (4 halves), converts, scales by w, fires one RED.v4 into out[dst].
// Gather traffic halves vs fp32 (128B/edge); RED stays fp32 (256B/edge).
// ---------------------------------------------------------------------------
__global__ __launch_bounds__(256) void scatter_kernel(
    const float* __restrict__ w,
    const int*   __restrict__ src,
    const int*   __restrict__ dst,
    float*       __restrict__ out)
{
    unsigned t    = blockIdx.x * blockDim.x + threadIdx.x;
    unsigned e    = t >> 4;
    unsigned lane = t & 15;
    if (e >= N_EDGES) return;

    int   s  = __ldg(src + e);
    int   d  = __ldg(dst + e);
    float we = __ldg(w + e);

    const uint2* yp = (const uint2*)(g_Y + (size_t)s * DIM) + lane;
    uint2 yv = *yp;
    __half2 h0 = *(__half2*)&yv.x;
    __half2 h1 = *(__half2*)&yv.y;
    float2 f0 = __half22float2(h0);
    float2 f1 = __half22float2(h1);

    float* p = out + (size_t)d * DIM + lane * 4;
    asm volatile("red.global.add.v4.f32 [%0], {%1,%2,%3,%4};"
                 :: "l"(p), "f"(f0.x * we), "f"(f0.y * we),
                    "f"(f1.x * we), "f"(f1.y * we)
                 : "memory");

    if (lane == 0) atomicAdd(g_deg + d, 1.0f);
}

// ---------------------------------------------------------------------------
// Kernel 3: normalize out by 1/max(deg,1); reset g_deg for the next call.
// 16 threads per row (one float4 each) -> same-warp read-then-reset is safe.
// ---------------------------------------------------------------------------
__global__ __launch_bounds__(256) void normalize_kernel(float4* __restrict__ out4) {
    int idx = blockIdx.x * blockDim.x + threadIdx.x;
    if (idx >= N_NODES * DIM / 4) return;
    const int r    = idx >> 4;
    const int lane = idx & 15;

    float dinv = 1.0f / fmaxf(g_deg[r], 1.0f);
    float4 v = out4[idx];
    v.x *= dinv; v.y *= dinv; v.z *= dinv; v.w *= dinv;
    out4[idx] = v;

    if (lane == 0) g_deg[r] = 0.f;       // all readers of r are this warp
}

// ---------------------------------------------------------------------------
// kernel_launch: zero(out) -> Y=F@W -> scatter(Y) -> normalize.
// Inputs (metadata order): features, w, W, src, dst.  Output: float [N, 64].
// ---------------------------------------------------------------------------
extern "C" void kernel_launch(void* const* d_in, const int* in_sizes, int n_in,
                              void* d_out, int out_size)
{
    const float* feat = (const float*)d_in[0];
    const float* w    = (const float*)d_in[1];
    const float* Wm   = (const float*)d_in[2];
    const int*   src  = (const int*)d_in[3];
    const int*   dst  = (const int*)d_in[4];
    float*       out  = (float*)d_out;

    {
        int grid = (N_NODES * DIM / 4 + 255) / 256;
        zero_out_kernel<<<grid, 256>>>((float4*)out);
    }
    {
        int grid = (N_NODES + TROWS - 1) / TROWS;
        gemm_fw_kernel<<<grid, 256>>>(feat, Wm);
    }
    {
        long long threads = (long long)N_EDGES * 16;
        int grid = (int)((threads + 255) / 256);
        scatter_kernel<<<grid, 256>>>(w, src, dst, out);
    }
    {
        int grid = (N_NODES * DIM / 4 + 255) / 256;
        normalize_kernel<<<grid, 256>>>((float4*)out);
    }
}